// round 1
// baseline (speedup 1.0000x reference)
#include <cuda_runtime.h>
#include <cuda_bf16.h>

// Problem shape (fixed by the reference)
#define B_DIM 16
#define S_DIM 4096
#define D_DIM 1024
#define D_VEC (D_DIM / 4)        // 256 float4 per row
#define WARPS_PER_CTA 8
#define THREADS_PER_CTA (WARPS_PER_CTA * 32)

__global__ void zero_out_kernel(float* __restrict__ out, int n) {
    int i = blockIdx.x * blockDim.x + threadIdx.x;
    if (i < n) out[i] = 0.0f;
}

__global__ __launch_bounds__(THREADS_PER_CTA)
void icreward_kernel(const float*  __restrict__ x,       // (B,S,D)
                     const float*  __restrict__ W,       // (2,D)
                     const float*  __restrict__ bias,    // (2,)
                     const int*    __restrict__ lengths, // (B,)
                     float*        __restrict__ out)     // (B,)
{
    const int b   = blockIdx.y;
    const int len = lengths[b];
    const int s0  = blockIdx.x * WARPS_PER_CTA;

    // Whole CTA past the valid region: skip (this is the bandwidth win)
    if (s0 >= len) return;

    __shared__ float4 w0s[D_VEC];
    __shared__ float4 w1s[D_VEC];
    __shared__ float  warp_sums[WARPS_PER_CTA];

    const int tid  = threadIdx.x;
    const int wid  = tid / 32;
    const int lane = tid % 32;

    // Stage W into shared (coalesced, 256 float4 per row, 256 threads)
    {
        const float4* W0 = reinterpret_cast<const float4*>(W);
        const float4* W1 = reinterpret_cast<const float4*>(W + D_DIM);
        w0s[tid] = W0[tid];
        w1s[tid] = W1[tid];
    }
    __syncthreads();

    const int s = s0 + wid;
    float contrib = 0.0f;

    if (s < len) {
        const float4* xrow = reinterpret_cast<const float4*>(
            x + ((size_t)b * S_DIM + s) * D_DIM);

        float acc0 = 0.0f, acc1 = 0.0f;
        #pragma unroll
        for (int k = 0; k < 8; k++) {
            const int idx = lane + k * 32;          // coalesced across lanes
            float4 xv = xrow[idx];
            float4 w0 = w0s[idx];
            float4 w1 = w1s[idx];
            acc0 += xv.x * w0.x + xv.y * w0.y + xv.z * w0.z + xv.w * w0.w;
            acc1 += xv.x * w1.x + xv.y * w1.y + xv.z * w1.z + xv.w * w1.w;
        }

        // Warp reduction of both dots
        #pragma unroll
        for (int off = 16; off > 0; off >>= 1) {
            acc0 += __shfl_xor_sync(0xFFFFFFFFu, acc0, off);
            acc1 += __shfl_xor_sync(0xFFFFFFFFu, acc1, off);
        }

        if (lane == 0) {
            float f0 = acc0 + bias[0];
            float f1 = acc1 + bias[1];
            float gate = 1.0f / (1.0f + __expf(-f0));
            contrib = gate * f1;
        }
    }

    if (lane == 0) warp_sums[wid] = contrib;
    __syncthreads();

    // CTA reduction (8 values) by thread 0, one atomic per CTA
    if (tid == 0) {
        float s_cta = 0.0f;
        #pragma unroll
        for (int w = 0; w < WARPS_PER_CTA; w++) s_cta += warp_sums[w];
        atomicAdd(&out[b], s_cta);
    }
}

extern "C" void kernel_launch(void* const* d_in, const int* in_sizes, int n_in,
                              void* d_out, int out_size) {
    const float* x       = (const float*)d_in[0];  // (B,S,D) fp32
    const float* W       = (const float*)d_in[1];  // (2,D)   fp32
    const float* bias    = (const float*)d_in[2];  // (2,)    fp32
    const int*   lengths = (const int*)d_in[3];    // (B,)    int32
    float*       out     = (float*)d_out;          // (B,)    fp32

    zero_out_kernel<<<1, 32>>>(out, out_size);

    dim3 grid(S_DIM / WARPS_PER_CTA, B_DIM);       // (512, 16)
    icreward_kernel<<<grid, THREADS_PER_CTA>>>(x, W, bias, lengths, out);
}

// round 2
// speedup vs baseline: 1.0749x; 1.0749x over previous
#include <cuda_runtime.h>
#include <cuda_bf16.h>

// Problem shape (fixed by the reference)
#define B_DIM 16
#define S_DIM 4096
#define D_DIM 1024
#define D_VEC (D_DIM / 4)          // 256 float4 per weight row
#define WARPS_PER_CTA 8
#define THREADS_PER_CTA (WARPS_PER_CTA * 32)
#define TOKENS_PER_WARP 4
#define ITERS 2
#define TOKENS_PER_CTA (WARPS_PER_CTA * TOKENS_PER_WARP * ITERS)   // 64

__global__ void zero_out_kernel(float* __restrict__ out, int n) {
    int i = blockIdx.x * blockDim.x + threadIdx.x;
    if (i < n) out[i] = 0.0f;
}

__device__ __forceinline__ float warp_sum(float v) {
    #pragma unroll
    for (int off = 16; off > 0; off >>= 1)
        v += __shfl_xor_sync(0xFFFFFFFFu, v, off);
    return v;
}

__global__ __launch_bounds__(THREADS_PER_CTA, 2)
void icreward_kernel(const float*  __restrict__ x,       // (B,S,D)
                     const float*  __restrict__ W,       // (2,D)
                     const float*  __restrict__ bias,    // (2,)
                     const int*    __restrict__ lengths, // (B,)
                     float*        __restrict__ out)     // (B,)
{
    const int b   = blockIdx.y;
    const int len = lengths[b];
    const int s0  = blockIdx.x * TOKENS_PER_CTA;

    // Whole CTA past the valid region: skip (bandwidth win from length mask)
    if (s0 >= len) return;

    __shared__ float4 w0s[D_VEC];
    __shared__ float4 w1s[D_VEC];
    __shared__ float  warp_sums[WARPS_PER_CTA];

    const int tid  = threadIdx.x;
    const int wid  = tid >> 5;
    const int lane = tid & 31;

    // Stage W into shared once per CTA (256 threads, one float4 each per row)
    {
        const float4* W0 = reinterpret_cast<const float4*>(W);
        const float4* W1 = reinterpret_cast<const float4*>(W + D_DIM);
        w0s[tid] = W0[tid];
        w1s[tid] = W1[tid];
    }
    __syncthreads();

    const float b0v = bias[0];
    const float b1v = bias[1];
    const float* xb = x + (size_t)b * S_DIM * D_DIM;

    float wsum = 0.0f;   // meaningful on lane 0 only

    #pragma unroll
    for (int it = 0; it < ITERS; ++it) {
        const int sbase = s0 + it * (WARPS_PER_CTA * TOKENS_PER_WARP)
                             + wid * TOKENS_PER_WARP;
        if (sbase >= len) break;

        const float4* r0 = reinterpret_cast<const float4*>(xb + (size_t)(sbase + 0) * D_DIM);
        const float4* r1 = reinterpret_cast<const float4*>(xb + (size_t)(sbase + 1) * D_DIM);
        const float4* r2 = reinterpret_cast<const float4*>(xb + (size_t)(sbase + 2) * D_DIM);
        const float4* r3 = reinterpret_cast<const float4*>(xb + (size_t)(sbase + 3) * D_DIM);

        const bool v1 = (sbase + 1) < len;
        const bool v2 = (sbase + 2) < len;
        const bool v3 = (sbase + 3) < len;

        float a00 = 0.f, a10 = 0.f;   // token 0: dot(w0), dot(w1)
        float a01 = 0.f, a11 = 0.f;
        float a02 = 0.f, a12 = 0.f;
        float a03 = 0.f, a13 = 0.f;

        #pragma unroll
        for (int k = 0; k < 8; ++k) {
            const int idx = lane + k * 32;           // coalesced across lanes
            const float4 w0 = w0s[idx];
            const float4 w1 = w1s[idx];

            {
                float4 xv = r0[idx];
                a00 += xv.x * w0.x + xv.y * w0.y + xv.z * w0.z + xv.w * w0.w;
                a10 += xv.x * w1.x + xv.y * w1.y + xv.z * w1.z + xv.w * w1.w;
            }
            if (v1) {
                float4 xv = r1[idx];
                a01 += xv.x * w0.x + xv.y * w0.y + xv.z * w0.z + xv.w * w0.w;
                a11 += xv.x * w1.x + xv.y * w1.y + xv.z * w1.z + xv.w * w1.w;
            }
            if (v2) {
                float4 xv = r2[idx];
                a02 += xv.x * w0.x + xv.y * w0.y + xv.z * w0.z + xv.w * w0.w;
                a12 += xv.x * w1.x + xv.y * w1.y + xv.z * w1.z + xv.w * w1.w;
            }
            if (v3) {
                float4 xv = r3[idx];
                a03 += xv.x * w0.x + xv.y * w0.y + xv.z * w0.z + xv.w * w0.w;
                a13 += xv.x * w1.x + xv.y * w1.y + xv.z * w1.z + xv.w * w1.w;
            }
        }

        // Warp reductions (8 independent scalars, pipelined shuffles)
        a00 = warp_sum(a00);  a10 = warp_sum(a10);
        a01 = warp_sum(a01);  a11 = warp_sum(a11);
        a02 = warp_sum(a02);  a12 = warp_sum(a12);
        a03 = warp_sum(a03);  a13 = warp_sum(a13);

        if (lane == 0) {
            {
                float g = 1.0f / (1.0f + __expf(-(a00 + b0v)));
                wsum += g * (a10 + b1v);
            }
            if (v1) {
                float g = 1.0f / (1.0f + __expf(-(a01 + b0v)));
                wsum += g * (a11 + b1v);
            }
            if (v2) {
                float g = 1.0f / (1.0f + __expf(-(a02 + b0v)));
                wsum += g * (a12 + b1v);
            }
            if (v3) {
                float g = 1.0f / (1.0f + __expf(-(a03 + b0v)));
                wsum += g * (a13 + b1v);
            }
        }
    }

    if (lane == 0) warp_sums[wid] = wsum;
    __syncthreads();

    if (tid == 0) {
        float s_cta = 0.0f;
        #pragma unroll
        for (int w = 0; w < WARPS_PER_CTA; w++) s_cta += warp_sums[w];
        atomicAdd(&out[b], s_cta);
    }
}

extern "C" void kernel_launch(void* const* d_in, const int* in_sizes, int n_in,
                              void* d_out, int out_size) {
    const float* x       = (const float*)d_in[0];  // (B,S,D) fp32
    const float* W       = (const float*)d_in[1];  // (2,D)   fp32
    const float* bias    = (const float*)d_in[2];  // (2,)    fp32
    const int*   lengths = (const int*)d_in[3];    // (B,)    int32
    float*       out     = (float*)d_out;          // (B,)    fp32

    zero_out_kernel<<<1, 32>>>(out, out_size);

    dim3 grid(S_DIM / TOKENS_PER_CTA, B_DIM);      // (64, 16)
    icreward_kernel<<<grid, THREADS_PER_CTA>>>(x, W, bias, lengths, out);
}

// round 3
// speedup vs baseline: 1.0819x; 1.0065x over previous
#include <cuda_runtime.h>
#include <cuda_bf16.h>

// Problem shape (fixed by the reference)
#define B_DIM 16
#define S_DIM 4096
#define D_DIM 1024
#define D_VEC (D_DIM / 4)          // 256 float4 per weight row
#define WARPS_PER_CTA 8
#define THREADS_PER_CTA (WARPS_PER_CTA * 32)
#define TOKENS_PER_WARP 2
#define ITERS 4
#define TOKENS_PER_CTA (WARPS_PER_CTA * TOKENS_PER_WARP * ITERS)   // 64

__global__ void zero_out_kernel(float* __restrict__ out, int n) {
    int i = blockIdx.x * blockDim.x + threadIdx.x;
    if (i < n) out[i] = 0.0f;
}

__device__ __forceinline__ float warp_sum(float v) {
    #pragma unroll
    for (int off = 16; off > 0; off >>= 1)
        v += __shfl_xor_sync(0xFFFFFFFFu, v, off);
    return v;
}

__global__ __launch_bounds__(THREADS_PER_CTA, 4)   // cap regs at 64 -> 4 CTAs/SM
void icreward_kernel(const float*  __restrict__ x,       // (B,S,D)
                     const float*  __restrict__ W,       // (2,D)
                     const float*  __restrict__ bias,    // (2,)
                     const int*    __restrict__ lengths, // (B,)
                     float*        __restrict__ out)     // (B,)
{
    const int b   = blockIdx.y;
    const int len = lengths[b];
    const int s0  = blockIdx.x * TOKENS_PER_CTA;

    // Whole CTA past the valid region: skip (bandwidth win from length mask)
    if (s0 >= len) return;

    __shared__ float4 w0s[D_VEC];
    __shared__ float4 w1s[D_VEC];
    __shared__ float  warp_sums[WARPS_PER_CTA];

    const int tid  = threadIdx.x;
    const int wid  = tid >> 5;
    const int lane = tid & 31;

    // Stage W into shared once per CTA
    {
        const float4* W0 = reinterpret_cast<const float4*>(W);
        const float4* W1 = reinterpret_cast<const float4*>(W + D_DIM);
        w0s[tid] = W0[tid];
        w1s[tid] = W1[tid];
    }
    __syncthreads();

    const float b0v = bias[0];
    const float b1v = bias[1];
    const float* xb = x + (size_t)b * S_DIM * D_DIM;

    float wsum = 0.0f;   // meaningful on lane 0 only

    #pragma unroll
    for (int it = 0; it < ITERS; ++it) {
        const int sbase = s0 + it * (WARPS_PER_CTA * TOKENS_PER_WARP)
                             + wid * TOKENS_PER_WARP;
        if (sbase >= len) break;

        // one base pointer; second token at compile-time offset (+D_VEC float4s)
        const float4* r = reinterpret_cast<const float4*>(xb + (size_t)sbase * D_DIM);
        const bool v1 = (sbase + 1) < len;

        float a00 = 0.f, a10 = 0.f;   // token 0: dot(w0), dot(w1)
        float a01 = 0.f, a11 = 0.f;   // token 1

        #pragma unroll
        for (int k = 0; k < 8; ++k) {
            const int idx = lane + k * 32;            // coalesced across lanes
            const float4 w0 = w0s[idx];
            const float4 w1 = w1s[idx];

            {
                float4 xv = __ldcs(&r[idx]);          // streaming, evict-first
                a00 += xv.x * w0.x + xv.y * w0.y + xv.z * w0.z + xv.w * w0.w;
                a10 += xv.x * w1.x + xv.y * w1.y + xv.z * w1.z + xv.w * w1.w;
            }
            if (v1) {
                float4 xv = __ldcs(&r[idx + D_VEC]);  // +16KB immediate offset
                a01 += xv.x * w0.x + xv.y * w0.y + xv.z * w0.z + xv.w * w0.w;
                a11 += xv.x * w1.x + xv.y * w1.y + xv.z * w1.z + xv.w * w1.w;
            }
        }

        a00 = warp_sum(a00);  a10 = warp_sum(a10);
        a01 = warp_sum(a01);  a11 = warp_sum(a11);

        if (lane == 0) {
            {
                float g = 1.0f / (1.0f + __expf(-(a00 + b0v)));
                wsum += g * (a10 + b1v);
            }
            if (v1) {
                float g = 1.0f / (1.0f + __expf(-(a01 + b0v)));
                wsum += g * (a11 + b1v);
            }
        }
    }

    if (lane == 0) warp_sums[wid] = wsum;
    __syncthreads();

    if (tid == 0) {
        float s_cta = 0.0f;
        #pragma unroll
        for (int w = 0; w < WARPS_PER_CTA; w++) s_cta += warp_sums[w];
        atomicAdd(&out[b], s_cta);
    }
}

extern "C" void kernel_launch(void* const* d_in, const int* in_sizes, int n_in,
                              void* d_out, int out_size) {
    const float* x       = (const float*)d_in[0];  // (B,S,D) fp32
    const float* W       = (const float*)d_in[1];  // (2,D)   fp32
    const float* bias    = (const float*)d_in[2];  // (2,)    fp32
    const int*   lengths = (const int*)d_in[3];    // (B,)    int32
    float*       out     = (float*)d_out;          // (B,)    fp32

    zero_out_kernel<<<1, 32>>>(out, out_size);

    dim3 grid(S_DIM / TOKENS_PER_CTA, B_DIM);      // (64, 16)
    icreward_kernel<<<grid, THREADS_PER_CTA>>>(x, W, bias, lengths, out);
}